// round 1
// baseline (speedup 1.0000x reference)
#include <cuda_runtime.h>

// ---------------- problem constants ----------------
#define NZ     300
#define NX     400
#define NPML   32
#define NPAD   0
#define NZP    (NZ + 2*NPML + NPAD)     // 364
#define NXP    (NX + 2*NPML)            // 464
#define NXPP   480                      // pitch (floats), 1920B rows
#define NSTEPS 200
#define NSHOTS 2
#define DXC    0.01f
#define DTC    0.001f
#define SRC_Z  (NPML + 2)               // 34
#define REC_Z  (NPML + 2)               // 34

#define FSZ (NZP * NXPP)

// ---------------- device state (static, no allocs) ----------------
__device__ float g_lam[FSZ];
__device__ float g_lam2mu[FSZ];
__device__ float g_mu[FSZ];
__device__ float g_dtrho[FSZ];
__device__ float g_damp[FSZ];

__device__ float g_vx [NSHOTS][FSZ];
__device__ float g_vz [NSHOTS][FSZ];
__device__ float g_sxx[NSHOTS][FSZ];
__device__ float g_szz[NSHOTS][FSZ];
__device__ float g_sxz[NSHOTS][FSZ];

__device__ float g_recs[NSHOTS * NSTEPS * NX];
__device__ int   g_sid [NSHOTS];
__device__ int   g_srcx[NSHOTS];

// ---------------- prep: pad models, coefficients, sponge, zero fields ----------------
__global__ void fwi_prep(const float* __restrict__ Vp,
                         const float* __restrict__ Vs,
                         const float* __restrict__ Den,
                         const float* __restrict__ Mask,
                         const int*   __restrict__ ShotIds)
{
    int j = blockIdx.x * blockDim.x + threadIdx.x;
    int i = blockIdx.y * blockDim.y + threadIdx.y;
    if (i >= NZP || j >= NXP) return;

    int ip = i - NPML; ip = ip < 0 ? 0 : (ip > NZ - 1 ? NZ - 1 : ip);
    int jp = j - NPML; jp = jp < 0 ? 0 : (jp > NX - 1 ? NX - 1 : jp);

    float vp  = Vp [ip * NX + jp];
    float vs  = Vs [ip * NX + jp];
    float den = Den[ip * NX + jp];
    float m   = Mask[i * NXP + j];

    // forward of the stop_gradient mixing (identity in value)
    vp  = m * vp  + (1.0f - m) * vp;
    vs  = m * vs  + (1.0f - m) * vs;
    den = m * den + (1.0f - m) * den;

    float mu  = vs * vs * den / 1000000.0f;
    float lam = (vp * vp - 2.0f * vs * vs) * den / 1000000.0f;

    int idx = i * NXPP + j;
    g_lam[idx]    = lam;
    g_mu[idx]     = mu;
    g_lam2mu[idx] = lam + 2.0f * mu;
    g_dtrho[idx]  = DTC / den;

    // sponge
    float a1 = (float)(NPML - i);
    float a2 = (float)(i - (NZP - 1 - NPML - NPAD));
    float dz = fmaxf(a1, a2); dz = fminf(fmaxf(dz, 0.0f), (float)NPML) / (float)NPML;
    float b1 = (float)(NPML - j);
    float b2 = (float)(j - (NXP - 1 - NPML));
    float dxs = fmaxf(b1, b2); dxs = fminf(fmaxf(dxs, 0.0f), (float)NPML) / (float)NPML;
    g_damp[idx] = expf(-0.1f * (dz * dz + dxs * dxs));

    // zero wavefields (both shots)
    #pragma unroll
    for (int s = 0; s < NSHOTS; ++s) {
        g_vx [s][idx] = 0.0f;
        g_vz [s][idx] = 0.0f;
        g_sxx[s][idx] = 0.0f;
        g_szz[s][idx] = 0.0f;
        g_sxz[s][idx] = 0.0f;
    }

    if (i == 0 && j < NSHOTS) {
        int id = ShotIds[j];
        g_sid[j]  = id;
        g_srcx[j] = NPML + 20 + id * ((NX - 40) / NSHOTS);
    }
}

// ---------------- velocity update + receiver record ----------------
__global__ void fwi_vel(int t)
{
    int j = blockIdx.x * 32 + threadIdx.x;
    int i = blockIdx.y * 8  + threadIdx.y;
    int s = blockIdx.z;
    if (i >= NZP || j >= NXP) return;

    int idx = i * NXPP + j;
    float damp  = g_damp[idx];
    float dtrho = g_dtrho[idx];

    const float* __restrict__ sxx = g_sxx[s];
    const float* __restrict__ szz = g_szz[s];
    const float* __restrict__ sxz = g_sxz[s];

    float sxx_c = sxx[idx];
    float sxx_r = (j + 1 < NXP) ? sxx[idx + 1]    : 0.0f;
    float sxz_c = sxz[idx];
    float sxz_u = (i > 0)       ? sxz[idx - NXPP] : 0.0f;
    float sxz_l = (j > 0)       ? sxz[idx - 1]    : 0.0f;
    float szz_c = szz[idx];
    float szz_d = (i + 1 < NZP) ? szz[idx + NXPP] : 0.0f;

    float vx = (g_vx[s][idx] + dtrho * ((sxx_r - sxx_c) / DXC + (sxz_c - sxz_u) / DXC)) * damp;
    float vz = (g_vz[s][idx] + dtrho * ((sxz_c - sxz_l) / DXC + (szz_d - szz_c) / DXC)) * damp;

    g_vx[s][idx] = vx;
    g_vz[s][idx] = vz;

    if (i == REC_Z && j >= NPML && j < NPML + NX) {
        g_recs[(s * NSTEPS + t) * NX + (j - NPML)] = vx;
    }
}

// ---------------- stress update + source injection ----------------
__global__ void fwi_str(int t, const float* __restrict__ Stf)
{
    int j = blockIdx.x * 32 + threadIdx.x;
    int i = blockIdx.y * 8  + threadIdx.y;
    int s = blockIdx.z;
    if (i >= NZP || j >= NXP) return;

    int idx = i * NXPP + j;
    float damp = g_damp[idx];

    const float* __restrict__ vx = g_vx[s];
    const float* __restrict__ vz = g_vz[s];

    float vx_c = vx[idx];
    float vx_l = (j > 0)       ? vx[idx - 1]    : 0.0f;
    float vx_d = (i + 1 < NZP) ? vx[idx + NXPP] : 0.0f;
    float vz_c = vz[idx];
    float vz_u = (i > 0)       ? vz[idx - NXPP] : 0.0f;
    float vz_r = (j + 1 < NXP) ? vz[idx + 1]    : 0.0f;

    float dvxdx = (vx_c - vx_l) / DXC;
    float dvzdz = (vz_c - vz_u) / DXC;

    float lam    = g_lam[idx];
    float lam2mu = g_lam2mu[idx];
    float mu     = g_mu[idx];

    float sxxn = (g_sxx[s][idx] + DTC * (lam2mu * dvxdx + lam    * dvzdz)) * damp;
    float szzn = (g_szz[s][idx] + DTC * (lam    * dvxdx + lam2mu * dvzdz)) * damp;
    float sxzn = (g_sxz[s][idx] + DTC * mu * ((vx_d - vx_c) / DXC + (vz_r - vz_c) / DXC)) * damp;

    if (i == SRC_Z && j == g_srcx[s]) {
        float sv = Stf[g_sid[s] * NSTEPS + t] * DTC;
        sxxn += sv;
        szzn += sv;
    }

    g_sxx[s][idx] = sxxn;
    g_szz[s][idx] = szzn;
    g_sxz[s][idx] = sxzn;
}

// ---------------- deterministic reduction: 0.5 * sum(recs^2) ----------------
__global__ void fwi_reduce(float* __restrict__ out)
{
    __shared__ double sh[1024];
    double acc = 0.0;
    const int n = NSHOTS * NSTEPS * NX;
    for (int k = threadIdx.x; k < n; k += 1024) {
        float v = g_recs[k];
        acc += (double)v * (double)v;
    }
    sh[threadIdx.x] = acc;
    __syncthreads();
    for (int ofs = 512; ofs > 0; ofs >>= 1) {
        if (threadIdx.x < ofs) sh[threadIdx.x] += sh[threadIdx.x + ofs];
        __syncthreads();
    }
    if (threadIdx.x == 0) out[0] = (float)(0.5 * sh[0]);
}

// ---------------- launcher ----------------
extern "C" void kernel_launch(void* const* d_in, const int* in_sizes, int n_in,
                              void* d_out, int out_size)
{
    const float* Vp      = (const float*)d_in[0];
    const float* Vs      = (const float*)d_in[1];
    const float* Den     = (const float*)d_in[2];
    const float* Stf     = (const float*)d_in[3];
    const float* Mask    = (const float*)d_in[4];
    const int*   ShotIds = (const int*)  d_in[5];
    float*       out     = (float*)d_out;
    (void)in_sizes; (void)n_in; (void)out_size;

    dim3 blk(32, 8, 1);
    dim3 grd2((NXP + 31) / 32, (NZP + 7) / 8, 1);
    dim3 grd3((NXP + 31) / 32, (NZP + 7) / 8, NSHOTS);

    fwi_prep<<<grd2, blk>>>(Vp, Vs, Den, Mask, ShotIds);

    for (int t = 0; t < NSTEPS; ++t) {
        fwi_vel<<<grd3, blk>>>(t);
        fwi_str<<<grd3, blk>>>(t, Stf);
    }

    fwi_reduce<<<1, 1024>>>(out);
}